// round 5
// baseline (speedup 1.0000x reference)
#include <cuda_runtime.h>

#define NQ 4
#define NL 8
#define NGATES ((NL + 1) * NQ)

typedef unsigned long long ull;

// ---------- packed f32x2 helpers ----------
__device__ __forceinline__ ull pk2(float lo, float hi) {
    ull r; asm("mov.b64 %0, {%1,%2};" : "=l"(r) : "f"(lo), "f"(hi)); return r;
}
__device__ __forceinline__ ull bc2(float x) { return pk2(x, x); }
__device__ __forceinline__ void up2(ull v, float& lo, float& hi) {
    asm("mov.b64 {%0,%1}, %2;" : "=f"(lo), "=f"(hi) : "l"(v));
}
__device__ __forceinline__ ull fma2(ull a, ull b, ull c) {
    ull d; asm("fma.rn.f32x2 %0, %1, %2, %3;" : "=l"(d) : "l"(a), "l"(b), "l"(c)); return d;
}
__device__ __forceinline__ ull mul2(ull a, ull b) {
    ull d; asm("mul.rn.f32x2 %0, %1, %2;" : "=l"(d) : "l"(a), "l"(b)); return d;
}

#define SGN 0x8000000080000000ULL

// Fused U = RZ*RY*RX gates, each coefficient duplicated into both f32 lanes.
__device__ ull g_gates2[NGATES * 8];

__global__ void precompute_gates_kernel(const float* __restrict__ theta) {
    int g = blockIdx.x * blockDim.x + threadIdx.x;
    if (g >= NGATES) return;
    float a = theta[g * 3 + 0];
    float b = theta[g * 3 + 1];
    float c = theta[g * 3 + 2];
    float sa, ca, sb, cb, sc, cc;
    sincosf(0.5f * a, &sa, &ca);
    sincosf(0.5f * b, &sb, &cb);
    sincosf(0.5f * c, &sc, &cc);
    float m00r = cb * ca, m00i =  sb * sa;
    float m01r = -sb * ca, m01i = -cb * sa;
    float m10r =  sb * ca, m10i = -cb * sa;
    float m11r =  cb * ca, m11i = -sb * sa;
    float o[8];
    o[0] = m00r * cc + m00i * sc; o[1] = m00i * cc - m00r * sc;
    o[2] = m01r * cc + m01i * sc; o[3] = m01i * cc - m01r * sc;
    o[4] = m10r * cc - m10i * sc; o[5] = m10i * cc + m10r * sc;
    o[6] = m11r * cc - m11i * sc; o[7] = m11i * cc + m11r * sc;
#pragma unroll
    for (int k = 0; k < 8; k++) {
        ull d = (ull)__float_as_uint(o[k]);
        g_gates2[g * 8 + k] = d | (d << 32);
    }
}

// Apply the packed 2x2 gate (v0..v7, n1,n3,n5,n7 in scope) to slot pair (k,j)
#define APPLY_PAIR(k, j) { \
    ull t0r = fma2(n3, I[j], fma2(v2, R[j], fma2(n1, I[k], mul2(v0, R[k])))); \
    ull t0i = fma2(v3, R[j], fma2(v2, I[j], fma2(v1, R[k], mul2(v0, I[k])))); \
    ull t1r = fma2(n7, I[j], fma2(v6, R[j], fma2(n5, I[k], mul2(v4, R[k])))); \
    ull t1i = fma2(v7, R[j], fma2(v6, I[j], fma2(v5, R[k], mul2(v4, I[k])))); \
    R[k] = t0r; I[k] = t0i; R[j] = t1r; I[j] = t1i; }

__global__ __launch_bounds__(256)
void pqc_kernel(const float4* __restrict__ x,
                const float* __restrict__ lmbd,
                float* __restrict__ out, int B2) {
    __shared__ ull sh_g[NGATES * 8];
    __shared__ float sh_l[NL * NQ];
    for (int i = threadIdx.x; i < NGATES * 8; i += blockDim.x) sh_g[i] = g_gates2[i];
    for (int i = threadIdx.x; i < NL * NQ; i += blockDim.x) sh_l[i] = 0.5f * lmbd[i];
    __syncthreads();

    int t = blockIdx.x * blockDim.x + threadIdx.x;
    if (t >= B2) return;

    float4 xa = x[t];
    float4 xb = x[t + B2];
    float xqa[NQ] = {xa.x, xa.y, xa.z, xa.w};
    float xqb[NQ] = {xb.x, xb.y, xb.z, xb.w};

    // Lane-packed state: R[i]/I[i] hold (sampleA amp_i, sampleB amp_i)
    ull R[16], I[16];

    // ---- layer-0 fixed gates on |0000>: tensor product of gate columns 0 ----
    {
        const float* shf = (const float*)sh_g;  // lo lane of duplicated coeffs
        // gate g column 0: entries (u00r,u00i)=idx 0,1 ; (u10r,u10i)=idx 4,5
        float A0r = shf[(0 * 8 + 0) * 2], A0i = shf[(0 * 8 + 1) * 2];
        float A1r = shf[(0 * 8 + 4) * 2], A1i = shf[(0 * 8 + 5) * 2];
        float B0r = shf[(1 * 8 + 0) * 2], B0i = shf[(1 * 8 + 1) * 2];
        float B1r = shf[(1 * 8 + 4) * 2], B1i = shf[(1 * 8 + 5) * 2];
        float C0r = shf[(2 * 8 + 0) * 2], C0i = shf[(2 * 8 + 1) * 2];
        float C1r = shf[(2 * 8 + 4) * 2], C1i = shf[(2 * 8 + 5) * 2];
        float D0r = shf[(3 * 8 + 0) * 2], D0i = shf[(3 * 8 + 1) * 2];
        float D1r = shf[(3 * 8 + 4) * 2], D1i = shf[(3 * 8 + 5) * 2];
        float abr[4], abi[4], cdr[4], cdi[4];
        abr[0] = A0r * B0r - A0i * B0i; abi[0] = A0r * B0i + A0i * B0r;
        abr[1] = A0r * B1r - A0i * B1i; abi[1] = A0r * B1i + A0i * B1r;
        abr[2] = A1r * B0r - A1i * B0i; abi[2] = A1r * B0i + A1i * B0r;
        abr[3] = A1r * B1r - A1i * B1i; abi[3] = A1r * B1i + A1i * B1r;
        cdr[0] = C0r * D0r - C0i * D0i; cdi[0] = C0r * D0i + C0i * D0r;
        cdr[1] = C0r * D1r - C0i * D1i; cdi[1] = C0r * D1i + C0i * D1r;
        cdr[2] = C1r * D0r - C1i * D0i; cdi[2] = C1r * D0i + C1i * D0r;
        cdr[3] = C1r * D1r - C1i * D1i; cdi[3] = C1r * D1i + C1i * D1r;
#pragma unroll
        for (int i = 0; i < 16; i++) {
            int hi = i >> 2, lo = i & 3;
            float vr = abr[hi] * cdr[lo] - abi[hi] * cdi[lo];
            float vi = abr[hi] * cdi[lo] + abi[hi] * cdr[lo];
            R[i] = bc2(vr);
            I[i] = bc2(vi);
        }
    }

    // Loop covers: CZ_l then V = U(l+1)*RX_l for l=0..NL-1 (U(NL) consumed at l=NL-1).
    for (int l = 0; l < NL; l++) {
        // ---- CZ ring: sign flip on basis states {3,6,9,12} (ALU pipe) ----
        R[3] ^= SGN; I[3] ^= SGN; R[6] ^= SGN; I[6] ^= SGN;
        R[9] ^= SGN; I[9] ^= SGN; R[12] ^= SGN; I[12] ^= SGN;

        const ull* gl = &sh_g[(l + 1) * NQ * 8];
        const float* ll = &sh_l[l * NQ];

#pragma unroll
        for (int q = 0; q < NQ; q++) {
            float hl = ll[q];
            float sA, cA, sB, cB;
            __sincosf(hl * xqa[q], &sA, &cA);
            __sincosf(hl * xqb[q], &sB, &cB);
            ull c2 = pk2(cA, cB), s2 = pk2(sA, sB);
            ull ns2 = s2 ^ SGN;
            ull u0 = gl[q * 8 + 0], u1 = gl[q * 8 + 1], u2 = gl[q * 8 + 2], u3 = gl[q * 8 + 3];
            ull u4 = gl[q * 8 + 4], u5 = gl[q * 8 + 5], u6 = gl[q * 8 + 6], u7 = gl[q * 8 + 7];
            // V = U * RX(ang), packed over the two samples
            ull v0 = fma2(c2, u0, mul2(s2, u3));
            ull v1 = fma2(c2, u1, mul2(ns2, u2));
            ull v2 = fma2(s2, u1, mul2(c2, u2));
            ull v3 = fma2(c2, u3, mul2(ns2, u0));
            ull v4 = fma2(c2, u4, mul2(s2, u7));
            ull v5 = fma2(c2, u5, mul2(ns2, u6));
            ull v6 = fma2(s2, u5, mul2(c2, u6));
            ull v7 = fma2(c2, u7, mul2(ns2, u4));
            ull n1 = v1 ^ SGN, n3 = v3 ^ SGN, n5 = v5 ^ SGN, n7 = v7 ^ SGN;

            if (q == 0) {
                APPLY_PAIR(0, 8)  APPLY_PAIR(1, 9)  APPLY_PAIR(2, 10) APPLY_PAIR(3, 11)
                APPLY_PAIR(4, 12) APPLY_PAIR(5, 13) APPLY_PAIR(6, 14) APPLY_PAIR(7, 15)
            } else if (q == 1) {
                APPLY_PAIR(0, 4)  APPLY_PAIR(1, 5)  APPLY_PAIR(2, 6)  APPLY_PAIR(3, 7)
                APPLY_PAIR(8, 12) APPLY_PAIR(9, 13) APPLY_PAIR(10, 14) APPLY_PAIR(11, 15)
            } else if (q == 2) {
                APPLY_PAIR(0, 2)  APPLY_PAIR(1, 3)  APPLY_PAIR(4, 6)  APPLY_PAIR(5, 7)
                APPLY_PAIR(8, 10) APPLY_PAIR(9, 11) APPLY_PAIR(12, 14) APPLY_PAIR(13, 15)
            } else {
                APPLY_PAIR(0, 1)  APPLY_PAIR(2, 3)  APPLY_PAIR(4, 5)  APPLY_PAIR(6, 7)
                APPLY_PAIR(8, 9)  APPLY_PAIR(10, 11) APPLY_PAIR(12, 13) APPLY_PAIR(14, 15)
            }
        }
    }

    // ---- <Z0 Z1 Z2 Z3> : parity(+) on {0,3,5,6,9,10,12,15} ----
    ull accP = 0, accN = 0;
#pragma unroll
    for (int i = 0; i < 16; i++) {
        const int b0 = (i >> 3) & 1, b1 = (i >> 2) & 1, b2 = (i >> 1) & 1, b3 = i & 1;
        if (((b0 ^ b1 ^ b2 ^ b3) & 1) == 0) {
            accP = fma2(R[i], R[i], accP); accP = fma2(I[i], I[i], accP);
        } else {
            accN = fma2(R[i], R[i], accN); accN = fma2(I[i], I[i], accN);
        }
    }
    float pL, pH, nL, nH;
    up2(accP, pL, pH); up2(accN, nL, nH);
    out[t]      = pL - nL;
    out[t + B2] = pH - nH;
}

extern "C" void kernel_launch(void* const* d_in, const int* in_sizes, int n_in,
                              void* d_out, int out_size) {
    const float* x     = (const float*)d_in[0];   // [B, 4]
    const float* theta = (const float*)d_in[1];   // [1, 108]
    const float* lmbd  = (const float*)d_in[2];   // [32]
    float* out = (float*)d_out;                   // [B, 1]
    int B = in_sizes[0] / NQ;
    int B2 = B / 2;

    precompute_gates_kernel<<<1, 64>>>(theta);
    int threads = 256;
    int blocks = (B2 + threads - 1) / threads;
    pqc_kernel<<<blocks, threads>>>((const float4*)x, lmbd, out, B2);
}

// round 6
// speedup vs baseline: 1.0376x; 1.0376x over previous
#include <cuda_runtime.h>

#define NQ 4
#define NL 8
#define NGATES ((NL + 1) * NQ)

typedef unsigned long long ull;

// ---------- packed f32x2 helpers (Blackwell FFMA2 path) ----------
__device__ __forceinline__ ull pk2(float lo, float hi) {
    ull r; asm("mov.b64 %0, {%1,%2};" : "=l"(r) : "f"(lo), "f"(hi)); return r;
}
__device__ __forceinline__ ull bc2(float x) { return pk2(x, x); }
__device__ __forceinline__ void up2(ull v, float& lo, float& hi) {
    asm("mov.b64 {%0,%1}, %2;" : "=f"(lo), "=f"(hi) : "l"(v));
}
__device__ __forceinline__ ull fma2(ull a, ull b, ull c) {
    ull d; asm("fma.rn.f32x2 %0, %1, %2, %3;" : "=l"(d) : "l"(a), "l"(b), "l"(c)); return d;
}
__device__ __forceinline__ ull mul2(ull a, ull b) {
    ull d; asm("mul.rn.f32x2 %0, %1, %2;" : "=l"(d) : "l"(a), "l"(b)); return d;
}
__device__ __forceinline__ ull swap2(ull v) { float l, h; up2(v, l, h); return pk2(h, l); }

#define SGN2   0x8000000080000000ULL   // flip both lanes
#define SGN_LO 0x0000000080000000ULL   // flip lo lane only
#define SGN_HI 0x8000000000000000ULL   // flip hi lane only

// Precomputed fused U = RZ*RY*RX gates: 8 floats each
__device__ float g_gates[NGATES * 8];

__global__ void precompute_gates_kernel(const float* __restrict__ theta) {
    int g = blockIdx.x * blockDim.x + threadIdx.x;
    if (g >= NGATES) return;
    float a = theta[g * 3 + 0];
    float b = theta[g * 3 + 1];
    float c = theta[g * 3 + 2];
    float sa, ca, sb, cb, sc, cc;
    sincosf(0.5f * a, &sa, &ca);
    sincosf(0.5f * b, &sb, &cb);
    sincosf(0.5f * c, &sc, &cc);
    float m00r = cb * ca, m00i =  sb * sa;
    float m01r = -sb * ca, m01i = -cb * sa;
    float m10r =  sb * ca, m10i = -cb * sa;
    float m11r =  cb * ca, m11i = -sb * sa;
    float* o = &g_gates[g * 8];
    o[0] = m00r * cc + m00i * sc; o[1] = m00i * cc - m00r * sc;
    o[2] = m01r * cc + m01i * sc; o[3] = m01i * cc - m01r * sc;
    o[4] = m10r * cc - m10i * sc; o[5] = m10i * cc + m10r * sc;
    o[6] = m11r * cc - m11i * sc; o[7] = m11i * cc + m11r * sc;
}

struct G2 {
    ull p00r, p00i, n00i, p01r, p01i, n01i;
    ull p10r, p10i, n10i, p11r, p11i, n11i;
};

__device__ __forceinline__ void mkG(G2& g, const float v[8]) {
    g.p00r = bc2(v[0]); g.p00i = bc2(v[1]); g.n00i = g.p00i ^ SGN2;
    g.p01r = bc2(v[2]); g.p01i = bc2(v[3]); g.n01i = g.p01i ^ SGN2;
    g.p10r = bc2(v[4]); g.p10i = bc2(v[5]); g.n10i = g.p10i ^ SGN2;
    g.p11r = bc2(v[6]); g.p11i = bc2(v[7]); g.n11i = g.p11i ^ SGN2;
}

__device__ __forceinline__ void app(ull* R, ull* I, int k, int j, const G2& g) {
    ull t0r = fma2(g.n01i, I[j], fma2(g.p01r, R[j], fma2(g.n00i, I[k], mul2(g.p00r, R[k]))));
    ull t0i = fma2(g.p01i, R[j], fma2(g.p01r, I[j], fma2(g.p00i, R[k], mul2(g.p00r, I[k]))));
    ull t1r = fma2(g.n11i, I[j], fma2(g.p11r, R[j], fma2(g.n10i, I[k], mul2(g.p10r, R[k]))));
    ull t1i = fma2(g.p11i, R[j], fma2(g.p11r, I[j], fma2(g.p10i, R[k], mul2(g.p10r, I[k]))));
    R[k] = t0r; I[k] = t0i; R[j] = t1r; I[j] = t1i;
}

// Apply 2x2 gate v[8] on qubit Q to packed state (R,I). Slot k packs amps (k, k+8).
template <int Q>
__device__ __forceinline__ void apply_q(ull* R, ull* I, const float v[8]) {
    if (Q == 0) {
        ull Ar = pk2(v[0], v[6]), Ai = pk2(v[1], v[7]);
        ull Br = pk2(v[2], v[4]), Bi = pk2(v[3], v[5]);
        ull nAi = Ai ^ SGN2, nBi = Bi ^ SGN2;
#pragma unroll
        for (int k = 0; k < 8; k++) {
            ull Rs = swap2(R[k]), Is = swap2(I[k]);
            ull nr = fma2(nBi, Is, fma2(Br, Rs, fma2(nAi, I[k], mul2(Ar, R[k]))));
            ull ni = fma2(Bi, Rs, fma2(Br, Is, fma2(Ai, R[k], mul2(Ar, I[k]))));
            R[k] = nr; I[k] = ni;
        }
    } else {
        G2 g; mkG(g, v);
        if (Q == 1)      { app(R, I, 0, 4, g); app(R, I, 1, 5, g); app(R, I, 2, 6, g); app(R, I, 3, 7, g); }
        else if (Q == 2) { app(R, I, 0, 2, g); app(R, I, 1, 3, g); app(R, I, 4, 6, g); app(R, I, 5, 7, g); }
        else             { app(R, I, 0, 1, g); app(R, I, 2, 3, g); app(R, I, 4, 5, g); app(R, I, 6, 7, g); }
    }
}

// V = U * RX(ang) with s=sin(ang), c=cos(ang) precomputed
__device__ __forceinline__ void buildV(float v[8], const float* u, float s, float c) {
    v[0] = c * u[0] + s * u[3];  v[1] = c * u[1] - s * u[2];
    v[2] = s * u[1] + c * u[2];  v[3] = c * u[3] - s * u[0];
    v[4] = c * u[4] + s * u[7];  v[5] = c * u[5] - s * u[6];
    v[6] = s * u[5] + c * u[6];  v[7] = c * u[7] - s * u[4];
}

__device__ __forceinline__ float parity_exp(const ull* R, const ull* I) {
    // slot popcount even {0,3,5,6}: lane parity (+,-); odd {1,2,4,7}: (-,+)
    ull accA = 0, accB = 0;
#pragma unroll
    for (int k = 0; k < 8; k++) {
        bool even = (k == 0 || k == 3 || k == 5 || k == 6);
        if (even) { accA = fma2(R[k], R[k], accA); accA = fma2(I[k], I[k], accA); }
        else      { accB = fma2(R[k], R[k], accB); accB = fma2(I[k], I[k], accB); }
    }
    float aL, aH, bL, bH;
    up2(accA, aL, aH); up2(accB, bL, bH);
    return (aL - aH) - (bL - bH);
}

__global__ __launch_bounds__(128, 4)
void pqc_kernel(const float4* __restrict__ x,
                const float* __restrict__ lmbd,
                float* __restrict__ out, int B2) {
    __shared__ float sh_g[NGATES * 8];
    __shared__ float sh_l[NL * NQ];
    for (int i = threadIdx.x; i < NGATES * 8; i += blockDim.x) sh_g[i] = g_gates[i];
    for (int i = threadIdx.x; i < NL * NQ; i += blockDim.x) sh_l[i] = 0.5f * lmbd[i];
    __syncthreads();

    int t = blockIdx.x * blockDim.x + threadIdx.x;
    if (t >= B2) return;

    float4 xa = x[t];
    float4 xb = x[t + B2];
    float xqa[NQ] = {xa.x, xa.y, xa.z, xa.w};
    float xqb[NQ] = {xb.x, xb.y, xb.z, xb.w};

    ull RA[8], IA[8], RB[8], IB[8];

    // ---- layer-0 fixed gates on |0000>: tensor product (sample-independent) ----
    {
        float q1r[2], q1i[2], q2r[2], q2i[2], q3r[2], q3i[2];
        q1r[0] = sh_g[8 + 0];  q1i[0] = sh_g[8 + 1];  q1r[1] = sh_g[8 + 4];  q1i[1] = sh_g[8 + 5];
        q2r[0] = sh_g[16 + 0]; q2i[0] = sh_g[16 + 1]; q2r[1] = sh_g[16 + 4]; q2i[1] = sh_g[16 + 5];
        q3r[0] = sh_g[24 + 0]; q3i[0] = sh_g[24 + 1]; q3r[1] = sh_g[24 + 4]; q3i[1] = sh_g[24 + 5];
        float a0r = sh_g[0], a0i = sh_g[1], a1r = sh_g[4], a1i = sh_g[5];
        ull Apr = pk2(a0r, a1r), Api = pk2(a0i, a1i), nApi = Api ^ SGN2;
        float wr[4], wi[4];
#pragma unroll
        for (int b2 = 0; b2 < 2; b2++)
#pragma unroll
            for (int b3 = 0; b3 < 2; b3++) {
                wr[b2 * 2 + b3] = q2r[b2] * q3r[b3] - q2i[b2] * q3i[b3];
                wi[b2 * 2 + b3] = q2r[b2] * q3i[b3] + q2i[b2] * q3r[b3];
            }
#pragma unroll
        for (int k = 0; k < 8; k++) {
            int b1 = k >> 2, w = k & 3;
            float vr = q1r[b1] * wr[w] - q1i[b1] * wi[w];
            float vi = q1r[b1] * wi[w] + q1i[b1] * wr[w];
            ull vbr = bc2(vr), vbi = bc2(vi);
            RA[k] = fma2(nApi, vbi, mul2(Apr, vbr));
            IA[k] = fma2(Api, vbr, mul2(Apr, vbi));
            RB[k] = RA[k]; IB[k] = IA[k];
        }
    }

    // Loop l=0..NL-1: CZ_l, then V = U(l+1)*RX_l (U(NL) consumed at l=NL-1; no epilogue).
    for (int l = 0; l < NL; l++) {
        // ---- CZ ring via sign-bit XOR (ALU pipe) ----
        // flips amps {3,6}: lo lane of slots 3,6; amps {9,12}: hi lane of slots 1,4
        RA[3] ^= SGN_LO; IA[3] ^= SGN_LO; RA[6] ^= SGN_LO; IA[6] ^= SGN_LO;
        RA[1] ^= SGN_HI; IA[1] ^= SGN_HI; RA[4] ^= SGN_HI; IA[4] ^= SGN_HI;
        RB[3] ^= SGN_LO; IB[3] ^= SGN_LO; RB[6] ^= SGN_LO; IB[6] ^= SGN_LO;
        RB[1] ^= SGN_HI; IB[1] ^= SGN_HI; RB[4] ^= SGN_HI; IB[4] ^= SGN_HI;

        const float* gl = &sh_g[(l + 1) * NQ * 8];
        const float* ll = &sh_l[l * NQ];

        // hoist all sincos for this layer (break MUFU -> consumer chains)
        float sAq[NQ], cAq[NQ], sBq[NQ], cBq[NQ];
#pragma unroll
        for (int q = 0; q < NQ; q++) {
            float lq = ll[q];
            __sincosf(lq * xqa[q], &sAq[q], &cAq[q]);
            __sincosf(lq * xqb[q], &sBq[q], &cBq[q]);
        }

#pragma unroll
        for (int q = 0; q < NQ; q++) {
            float u[8];
#pragma unroll
            for (int i = 0; i < 8; i++) u[i] = gl[q * 8 + i];
            float va[8], vb[8];
            buildV(va, u, sAq[q], cAq[q]);
            buildV(vb, u, sBq[q], cBq[q]);
            if (q == 0)      { apply_q<0>(RA, IA, va); apply_q<0>(RB, IB, vb); }
            else if (q == 1) { apply_q<1>(RA, IA, va); apply_q<1>(RB, IB, vb); }
            else if (q == 2) { apply_q<2>(RA, IA, va); apply_q<2>(RB, IB, vb); }
            else             { apply_q<3>(RA, IA, va); apply_q<3>(RB, IB, vb); }
        }
    }

    out[t] = parity_exp(RA, IA);
    out[t + B2] = parity_exp(RB, IB);
}

extern "C" void kernel_launch(void* const* d_in, const int* in_sizes, int n_in,
                              void* d_out, int out_size) {
    const float* x     = (const float*)d_in[0];   // [B, 4]
    const float* theta = (const float*)d_in[1];   // [1, 108]
    const float* lmbd  = (const float*)d_in[2];   // [32]
    float* out = (float*)d_out;                   // [B, 1]
    int B = in_sizes[0] / NQ;
    int B2 = B / 2;

    precompute_gates_kernel<<<1, 64>>>(theta);
    int threads = 128;
    int blocks = (B2 + threads - 1) / threads;
    pqc_kernel<<<blocks, threads>>>((const float4*)x, lmbd, out, B2);
}